// round 12
// baseline (speedup 1.0000x reference)
#include <cuda_runtime.h>
#include <cstdint>

typedef unsigned long long ull;

#define SEQ 64
#define DM 32
#define DI 64
#define HW 1024
#define BB_TOT 2048

#define FMA2(d, a, b, c) \
    asm("fma.rn.f32x2 %0, %1, %2, %3;" : "=l"(d) : "l"(a), "l"(b), "l"(c))
#define MUL2(d, a, b) \
    asm("mul.rn.f32x2 %0, %1, %2;" : "=l"(d) : "l"(a), "l"(b))
__device__ __forceinline__ ull pack2(float lo, float hi) {
    ull r; asm("mov.b64 %0, {%1, %2};" : "=l"(r) : "f"(lo), "f"(hi)); return r;
}
__device__ __forceinline__ float2 unpack2(ull v) {
    float2 f; asm("mov.b64 {%0, %1}, %2;" : "=f"(f.x), "=f"(f.y) : "l"(v)); return f;
}
__device__ __forceinline__ ull lds64(uint32_t a) {
    ull v; asm volatile("ld.shared.b64 %0, [%1];" : "=l"(v) : "r"(a)); return v;
}
__device__ __forceinline__ float4 lds128(uint32_t a) {
    float4 v;
    asm volatile("ld.shared.v4.f32 {%0,%1,%2,%3}, [%4];"
                 : "=f"(v.x), "=f"(v.y), "=f"(v.z), "=f"(v.w) : "r"(a));
    return v;
}

// scratch
__device__ float g_xr[BB_TOT * SEQ * DM];        // transposed input
__device__ float g_xt[BB_TOT * SEQ * DI];        // conv+silu output
__device__ float g_sz[BB_TOT * SEQ * DI];        // silu(z)
__device__ float g_dbc[BB_TOT * SEQ * 36];       // [0:16)B [16:32)C [32]dt0 [33]dt1

// ---------------- transpose: x [2][64][32][1024] -> g_xr [bb][t][m] ----------------
__global__ __launch_bounds__(256) void transpose_kernel(const float* __restrict__ x) {
    __shared__ float tile[DM][65];
    const int bi = blockIdx.x;
    const int c  = bi & 15;
    const int t  = (bi >> 4) & 63;
    const int b  = bi >> 10;
    const float* src = x + ((b * SEQ + t) * DM) * HW + c * 64;
    const int tid = threadIdx.x;
    #pragma unroll
    for (int i = 0; i < 8; i++) {
        int idx = tid + i * 256;
        tile[idx >> 6][idx & 63] = src[(idx >> 6) * HW + (idx & 63)];
    }
    __syncthreads();
    #pragma unroll
    for (int i = 0; i < 8; i++) {
        int idx = tid + i * 256;
        int hw = idx >> 5, m = idx & 31;
        g_xr[(b * HW + c * 64 + hw) * (SEQ * DM) + t * DM + m] = tile[m][hw];
    }
}

// ---------------- K1: parallel prelude (one seq per block) ----------------
__global__ __launch_bounds__(256, 2) void prelude_kernel(
    const float* __restrict__ in_proj_w, const float* __restrict__ conv_w,
    const float* __restrict__ conv_b, const float* __restrict__ x_proj_w)
{
    __shared__ float4 winp4[8][128];      // [qq][r]: r<64 xh rows, r>=64 z rows
    __shared__ float4 xpw4[8][64];        // B/C half-rows
    __shared__ ull    wdt_u[64];          // dt rows 0/1 pairs
    __shared__ float  xin_s[SEQ][DM];     // whole-sequence input (8KB)
    __shared__ float  xt_s[SEQ][64];      // interleaved xt (16KB)

    const int tid = threadIdx.x;
    const int bb = blockIdx.x;

    for (int idx = tid; idx < 1024; idx += 256) {
        int qq = idx >> 7, r = idx & 127;
        winp4[qq][r] = *(const float4*)&in_proj_w[r * DM + 4 * qq];
    }
    for (int idx = tid; idx < 512; idx += 256) {
        int qq = idx >> 6, i = idx & 63;
        int wi = i >> 5, li = i & 31;
        int row = 2 + 16 * wi + (li >> 1), half = li & 1;
        xpw4[qq][i] = *(const float4*)&x_proj_w[row * DI + 32 * half + 4 * qq];
    }
    if (tid < 64) {
        int wi = tid >> 5, li = tid & 31;
        float2 p = *(const float2*)&x_proj_w[wi * DI + 2 * li];
        wdt_u[tid] = pack2(p.x, p.y);
    }
    {   // load whole input sequence: 512 float4
        const float4* src = (const float4*)(g_xr + (size_t)bb * (SEQ * DM));
        float4* dst = (float4*)&xin_s[0][0];
        dst[tid] = src[tid];
        dst[tid + 256] = src[tid + 256];
    }
    __syncthreads();

    const int g = tid >> 6;               // t-group (0..3)
    const int d = tid & 63;               // channel

    // ---- phase A: in_proj + conv + silu for t in [16g, 16g+16) ----
    {
        ull wa[16], wz[16];
        #pragma unroll
        for (int qq = 0; qq < 8; qq++) {
            float4 a4 = winp4[qq][d];
            wa[2 * qq] = pack2(a4.x, a4.y);
            wa[2 * qq + 1] = pack2(a4.z, a4.w);
            float4 z4 = winp4[qq][64 + d];
            wz[2 * qq] = pack2(z4.x, z4.y);
            wz[2 * qq + 1] = pack2(z4.z, z4.w);
        }
        const float4 cw = *(const float4*)(conv_w + d * 4);
        const float cb = conv_b[d];
        const int xpos = ((d & 31) >> 2) * 8 + ((d & 32) ? 4 : 0) + (d & 3);
        const int t0 = 16 * g;
        float xm1 = 0.f, xm2 = 0.f, xm3 = 0.f;

        // conv warmup: recompute xh for t0-3..t0-1
        #pragma unroll
        for (int k = 3; k >= 1; k--) {
            const int t = t0 - k;
            float xh = 0.f;
            if (t >= 0) {
                ull ax = 0ull;
                const float4* xp4 = (const float4*)xin_s[t];
                #pragma unroll
                for (int qq = 0; qq < 8; qq++) {
                    float4 xv4 = xp4[qq];
                    FMA2(ax, wa[2 * qq], pack2(xv4.x, xv4.y), ax);
                    FMA2(ax, wa[2 * qq + 1], pack2(xv4.z, xv4.w), ax);
                }
                float2 fx = unpack2(ax);
                xh = fx.x + fx.y;
            }
            xm3 = xm2; xm2 = xm1; xm1 = xh;
        }

        float* xtg = g_xt + (size_t)bb * (SEQ * DI);
        float* szg = g_sz + (size_t)bb * (SEQ * DI);
        #pragma unroll 4
        for (int tt = 0; tt < 16; tt++) {
            const int t = t0 + tt;
            ull ax = 0ull, az = 0ull;
            const float4* xp4 = (const float4*)xin_s[t];
            #pragma unroll
            for (int qq = 0; qq < 8; qq++) {
                float4 xv4 = xp4[qq];
                ull lo = pack2(xv4.x, xv4.y);
                ull hi = pack2(xv4.z, xv4.w);
                FMA2(ax, wa[2 * qq], lo, ax);
                FMA2(az, wz[2 * qq], lo, az);
                FMA2(ax, wa[2 * qq + 1], hi, ax);
                FMA2(az, wz[2 * qq + 1], hi, az);
            }
            float2 fx = unpack2(ax), fz = unpack2(az);
            const float xh = fx.x + fx.y;
            const float z = fz.x + fz.y;
            float xc = cb;
            xc = fmaf(cw.x, xm3, xc);
            xc = fmaf(cw.y, xm2, xc);
            xc = fmaf(cw.z, xm1, xc);
            xc = fmaf(cw.w, xh, xc);
            xm3 = xm2; xm2 = xm1; xm1 = xh;
            const float xt = __fdividef(xc, 1.f + __expf(-xc));
            xt_s[t][xpos] = xt;
            xtg[t * DI + d] = xt;
            szg[t * DI + d] = __fdividef(z, 1.f + __expf(-z));
        }
    }
    __syncthreads();

    // ---- phase B: x_proj half-rows + dt for t in [16g, 16g+16) ----
    {
        const int i = tid & 63;
        const int l = tid & 31;
        const int ihalf = (tid >> 5) & 1;     // == i>>5
        ull wB[16];
        #pragma unroll
        for (int qq = 0; qq < 8; qq++) {
            float4 b4 = xpw4[qq][i];
            wB[2 * qq] = pack2(b4.x, b4.y);
            wB[2 * qq + 1] = pack2(b4.z, b4.w);
        }
        const float2 wdv = unpack2(wdt_u[i]);
        const uint32_t xt_a = (uint32_t)__cvta_generic_to_shared(&xt_s[0][0]);
        const uint32_t hoff = (uint32_t)(i & 1) * 16u;
        const int d0 = 2 * l;
        const int dtf = (d0 < 32) ? ((d0 >> 2) * 8 + (d0 & 3))
                                  : (((d0 - 32) >> 2) * 8 + 4 + (d0 & 3));
        const int pos = 16 * ihalf + (l >> 1);
        float* dbcg = g_dbc + (size_t)bb * (SEQ * 36);

        #pragma unroll 4
        for (int tt = 0; tt < 16; tt++) {
            const int t = 16 * g + tt;
            const uint32_t rowa = xt_a + (uint32_t)t * 256u;
            ull acc = 0ull;
            #pragma unroll
            for (int qq = 0; qq < 8; qq++) {
                float4 xv4 = lds128(rowa + (uint32_t)qq * 32u + hoff);
                FMA2(acc, wB[2 * qq], pack2(xv4.x, xv4.y), acc);
                FMA2(acc, wB[2 * qq + 1], pack2(xv4.z, xv4.w), acc);
            }
            float2 a2 = unpack2(acc);
            float partial = a2.x + a2.y;
            partial += __shfl_xor_sync(0xffffffffu, partial, 1);
            if (!(l & 1)) dbcg[t * 36 + pos] = partial;

            float2 xv = unpack2(lds64(rowa + (uint32_t)dtf * 4u));
            float u = fmaf(wdv.y, xv.y, wdv.x * xv.x);
            #pragma unroll
            for (int off = 16; off; off >>= 1)
                u += __shfl_xor_sync(0xffffffffu, u, off);
            if (l == 0) dbcg[t * 36 + 32 + ihalf] = u;
        }
    }
}

// ---------------- K2: scan (4 seqs per block, no main-loop barriers) ----------------
__global__ __launch_bounds__(256, 3) void scan_kernel(
    const float* __restrict__ dt_proj_w, const float* __restrict__ dt_proj_b,
    const float* __restrict__ A_log, const float* __restrict__ Dp,
    const float* __restrict__ out_proj_w, const float* __restrict__ lin1_w,
    const float* __restrict__ lin1_b, const float* __restrict__ lin2_w,
    const float* __restrict__ lin2_b, float* __restrict__ out)
{
    __shared__ float part_s[4][SEQ][2];
    __shared__ float wm_s[DM];
    __shared__ float v_s[DI];
    __shared__ float a_s[DI][18];
    __shared__ float c_s;
    __shared__ int   slow_s;

    const int tid = threadIdx.x;
    const int team = tid >> 6;
    const int d = tid & 63;
    const int w = (tid >> 5) & 1;
    const int l = tid & 31;

    if (tid == 0) slow_s = 0;
    if (tid < DM) {
        float acc = 0.f;
        #pragma unroll
        for (int k = 0; k < 16; k++) acc = fmaf(lin2_w[k], lin1_w[k * 32 + tid], acc);
        wm_s[tid] = acc;
    }
    if (tid == 0) {
        float c = lin2_b[0];
        #pragma unroll
        for (int k = 0; k < 16; k++) c = fmaf(lin2_w[k], lin1_b[k], c);
        c_s = c;
    }
    __syncthreads();
    if (tid < DI) {
        float acc = 0.f;
        #pragma unroll
        for (int m = 0; m < 32; m++) acc = fmaf(wm_s[m], out_proj_w[m * 64 + tid], acc);
        v_s[tid] = acc;
        int bad = 0;
        #pragma unroll
        for (int n = 0; n < 16; n++) {
            float a = -__expf(A_log[tid * 16 + n]);
            a_s[tid][n] = a;
            if (fabsf(a + (float)(n + 1)) > 1e-4f * (float)(n + 1)) bad = 1;
        }
        if (bad) atomicOr(&slow_s, 1);
    }
    __syncthreads();

    const float2 dtw = *(const float2*)(dt_proj_w + d * 2);
    const float dtb = dt_proj_b[d];
    const float dpv = Dp[d];
    const float vv = v_s[d];
    const int slow = slow_s;

    const int bb = blockIdx.x * 4 + team;
    const float* dbcg = g_dbc + (size_t)bb * (SEQ * 36);
    const float* xtg  = g_xt + (size_t)bb * (SEQ * DI);
    const float* szg  = g_sz + (size_t)bb * (SEQ * DI);

    ull h2[8];
    #pragma unroll
    for (int q = 0; q < 8; q++) h2[q] = 0ull;

    #pragma unroll 4
    for (int t = 0; t < SEQ; t++) {
        const float4* dbr = (const float4*)(dbcg + t * 36);
        float4 b40 = __ldg(dbr + 0), b41 = __ldg(dbr + 1);
        float4 b42 = __ldg(dbr + 2), b43 = __ldg(dbr + 3);
        float4 c40 = __ldg(dbr + 4), c41 = __ldg(dbr + 5);
        float4 c42 = __ldg(dbr + 6), c43 = __ldg(dbr + 7);
        const float2 uu = __ldg((const float2*)(dbcg + t * 36 + 32));
        const float xt = __ldg(xtg + t * DI + d);
        const float sz = __ldg(szg + t * DI + d);

        const float dpre = fmaf(dtw.x, uu.x, fmaf(dtw.y, uu.y, dtb));
        const float delta = dpre > 15.f ? dpre : __logf(1.f + __expf(dpre));
        const float du = delta * xt;
        const ull du2 = pack2(du, du);
        ull y2a = 0ull, y2b = 0ull;

        if (!slow) {
            const float r = __expf(-delta);
            const float rr = r * r;
            ull cur = pack2(r, rr);
            const ull rrd = pack2(rr, rr);
            #pragma unroll
            for (int qq = 0; qq < 4; qq++) {
                float4 b4 = (qq == 0) ? b40 : (qq == 1) ? b41 : (qq == 2) ? b42 : b43;
                float4 c4 = (qq == 0) ? c40 : (qq == 1) ? c41 : (qq == 2) ? c42 : c43;
                ull bp = pack2(b4.x, b4.y), cp = pack2(c4.x, c4.y);
                ull tmp;
                MUL2(tmp, bp, du2);
                FMA2(h2[2 * qq], cur, h2[2 * qq], tmp);
                FMA2(y2a, h2[2 * qq], cp, y2a);
                MUL2(cur, cur, rrd);
                bp = pack2(b4.z, b4.w); cp = pack2(c4.z, c4.w);
                MUL2(tmp, bp, du2);
                FMA2(h2[2 * qq + 1], cur, h2[2 * qq + 1], tmp);
                FMA2(y2b, h2[2 * qq + 1], cp, y2b);
                if (qq < 3) MUL2(cur, cur, rrd);
            }
        } else {
            #pragma unroll
            for (int qq = 0; qq < 4; qq++) {
                float4 b4 = (qq == 0) ? b40 : (qq == 1) ? b41 : (qq == 2) ? b42 : b43;
                float4 c4 = (qq == 0) ? c40 : (qq == 1) ? c41 : (qq == 2) ? c42 : c43;
                float4 ap = *(const float4*)&a_s[d][4 * qq];
                ull dA = pack2(__expf(delta * ap.x), __expf(delta * ap.y));
                ull bp = pack2(b4.x, b4.y), cp = pack2(c4.x, c4.y);
                ull tmp;
                MUL2(tmp, bp, du2);
                FMA2(h2[2 * qq], dA, h2[2 * qq], tmp);
                FMA2(y2a, h2[2 * qq], cp, y2a);
                dA = pack2(__expf(delta * ap.z), __expf(delta * ap.w));
                bp = pack2(b4.z, b4.w); cp = pack2(c4.z, c4.w);
                MUL2(tmp, bp, du2);
                FMA2(h2[2 * qq + 1], dA, h2[2 * qq + 1], tmp);
                FMA2(y2b, h2[2 * qq + 1], cp, y2b);
            }
        }
        float2 ya = unpack2(y2a), yb = unpack2(y2b);
        float y = (ya.x + ya.y) + (yb.x + yb.y);
        y = fmaf(xt, dpv, y);
        y *= sz;

        float acc = y * vv;
        #pragma unroll
        for (int off = 16; off; off >>= 1)
            acc += __shfl_xor_sync(0xffffffffu, acc, off);
        if (l == 0) part_s[team][t][w] = acc;
    }

    __syncthreads();
    {
        const int tt = tid >> 2;
        const int jj = tid & 3;
        const float val = part_s[jj][tt][0] + part_s[jj][tt][1] + c_s;
        const int obb = blockIdx.x * 4 + jj;
        out[(obb >> 10) * (SEQ * HW) + tt * HW + (obb & (HW - 1))] = val;
    }
}

extern "C" void kernel_launch(void* const* d_in, const int* in_sizes, int n_in,
                              void* d_out, int out_size) {
    const float* x         = (const float*)d_in[0];
    const float* in_proj_w = (const float*)d_in[1];
    const float* conv_w    = (const float*)d_in[2];
    const float* conv_b    = (const float*)d_in[3];
    const float* x_proj_w  = (const float*)d_in[4];
    const float* dt_proj_w = (const float*)d_in[5];
    const float* dt_proj_b = (const float*)d_in[6];
    const float* A_log     = (const float*)d_in[7];
    const float* Dp        = (const float*)d_in[8];
    const float* out_proj_w= (const float*)d_in[9];
    const float* lin1_w    = (const float*)d_in[10];
    const float* lin1_b    = (const float*)d_in[11];
    const float* lin2_w    = (const float*)d_in[12];
    const float* lin2_b    = (const float*)d_in[13];
    float* out = (float*)d_out;

    transpose_kernel<<<2048, 256>>>(x);
    prelude_kernel<<<2048, 256>>>(in_proj_w, conv_w, conv_b, x_proj_w);
    scan_kernel<<<512, 256>>>(dt_proj_w, dt_proj_b, A_log, Dp, out_proj_w,
                              lin1_w, lin1_b, lin2_w, lin2_b, out);
}

// round 13
// speedup vs baseline: 1.2377x; 1.2377x over previous
#include <cuda_runtime.h>
#include <cstdint>

typedef unsigned long long ull;

#define SEQ 64
#define DM 32
#define DI 64
#define HW 1024
#define BB_TOT 2048
#define REC 176                  // packed record: [0:64)xt [64:128)sz [128:144)B [144:160)C [160]dt0 [161]dt1
#define RECF4 44
#define TK 8                     // K2 tile steps

#define FMA2(d, a, b, c) \
    asm("fma.rn.f32x2 %0, %1, %2, %3;" : "=l"(d) : "l"(a), "l"(b), "l"(c))
#define MUL2(d, a, b) \
    asm("mul.rn.f32x2 %0, %1, %2;" : "=l"(d) : "l"(a), "l"(b))
__device__ __forceinline__ ull pack2(float lo, float hi) {
    ull r; asm("mov.b64 %0, {%1, %2};" : "=l"(r) : "f"(lo), "f"(hi)); return r;
}
__device__ __forceinline__ float2 unpack2(ull v) {
    float2 f; asm("mov.b64 {%0, %1}, %2;" : "=f"(f.x), "=f"(f.y) : "l"(v)); return f;
}
__device__ __forceinline__ ull lds64(uint32_t a) {
    ull v; asm volatile("ld.shared.b64 %0, [%1];" : "=l"(v) : "r"(a)); return v;
}
__device__ __forceinline__ float4 lds128(uint32_t a) {
    float4 v;
    asm volatile("ld.shared.v4.f32 {%0,%1,%2,%3}, [%4];"
                 : "=f"(v.x), "=f"(v.y), "=f"(v.z), "=f"(v.w) : "r"(a));
    return v;
}
__device__ __forceinline__ void cpasync16(uint32_t s, const void* g) {
    asm volatile("cp.async.cg.shared.global [%0], [%1], 16;" :: "r"(s), "l"(g));
}
#define CP_COMMIT() asm volatile("cp.async.commit_group;" ::: "memory")
#define CP_WAIT0()  asm volatile("cp.async.wait_group 0;" ::: "memory")

// scratch
__device__ float g_xr[BB_TOT * SEQ * DM];
__device__ float g_pk[(size_t)BB_TOT * SEQ * REC];

// ---------------- transpose ----------------
__global__ __launch_bounds__(256) void transpose_kernel(const float* __restrict__ x) {
    __shared__ float tile[DM][65];
    const int bi = blockIdx.x;
    const int c  = bi & 15;
    const int t  = (bi >> 4) & 63;
    const int b  = bi >> 10;
    const float* src = x + ((b * SEQ + t) * DM) * HW + c * 64;
    const int tid = threadIdx.x;
    #pragma unroll
    for (int i = 0; i < 8; i++) {
        int idx = tid + i * 256;
        tile[idx >> 6][idx & 63] = src[(idx >> 6) * HW + (idx & 63)];
    }
    __syncthreads();
    #pragma unroll
    for (int i = 0; i < 8; i++) {
        int idx = tid + i * 256;
        int hw = idx >> 5, m = idx & 31;
        g_xr[(b * HW + c * 64 + hw) * (SEQ * DM) + t * DM + m] = tile[m][hw];
    }
}

// ---------------- K1: parallel prelude (one seq per block) ----------------
__global__ __launch_bounds__(256, 2) void prelude_kernel(
    const float* __restrict__ in_proj_w, const float* __restrict__ conv_w,
    const float* __restrict__ conv_b, const float* __restrict__ x_proj_w)
{
    __shared__ float4 winp4[8][128];
    __shared__ float4 xpw4[8][64];
    __shared__ ull    wdt_u[64];
    __shared__ float  xin_s[SEQ][DM];
    __shared__ float  xt_s[SEQ][64];      // interleaved

    const int tid = threadIdx.x;
    const int bb = blockIdx.x;

    for (int idx = tid; idx < 1024; idx += 256) {
        int qq = idx >> 7, r = idx & 127;
        winp4[qq][r] = *(const float4*)&in_proj_w[r * DM + 4 * qq];
    }
    for (int idx = tid; idx < 512; idx += 256) {
        int qq = idx >> 6, i = idx & 63;
        int wi = i >> 5, li = i & 31;
        int row = 2 + 16 * wi + (li >> 1), half = i & 1;
        xpw4[qq][i] = *(const float4*)&x_proj_w[row * DI + 32 * half + 4 * qq];
    }
    if (tid < 64) {
        int wi = tid >> 5, li = tid & 31;
        float2 p = *(const float2*)&x_proj_w[wi * DI + 2 * li];
        wdt_u[tid] = pack2(p.x, p.y);
    }
    {
        const float4* src = (const float4*)(g_xr + (size_t)bb * (SEQ * DM));
        float4* dst = (float4*)&xin_s[0][0];
        dst[tid] = src[tid];
        dst[tid + 256] = src[tid + 256];
    }
    __syncthreads();

    const int g = tid >> 6;
    const int d = tid & 63;
    float* pkg = g_pk + (size_t)bb * (SEQ * REC);

    // ---- phase A: in_proj + conv + silu for t in [16g, 16g+16) ----
    {
        ull wa[16], wz[16];
        #pragma unroll
        for (int qq = 0; qq < 8; qq++) {
            float4 a4 = winp4[qq][d];
            wa[2 * qq] = pack2(a4.x, a4.y);
            wa[2 * qq + 1] = pack2(a4.z, a4.w);
            float4 z4 = winp4[qq][64 + d];
            wz[2 * qq] = pack2(z4.x, z4.y);
            wz[2 * qq + 1] = pack2(z4.z, z4.w);
        }
        const float4 cw = *(const float4*)(conv_w + d * 4);
        const float cb = conv_b[d];
        const int xpos = ((d & 31) >> 2) * 8 + ((d & 32) ? 4 : 0) + (d & 3);
        const int t0 = 16 * g;
        float xm1 = 0.f, xm2 = 0.f, xm3 = 0.f;

        #pragma unroll
        for (int k = 3; k >= 1; k--) {
            const int t = t0 - k;
            float xh = 0.f;
            if (t >= 0) {
                ull ax = 0ull;
                const float4* xp4 = (const float4*)xin_s[t];
                #pragma unroll
                for (int qq = 0; qq < 8; qq++) {
                    float4 xv4 = xp4[qq];
                    FMA2(ax, wa[2 * qq], pack2(xv4.x, xv4.y), ax);
                    FMA2(ax, wa[2 * qq + 1], pack2(xv4.z, xv4.w), ax);
                }
                float2 fx = unpack2(ax);
                xh = fx.x + fx.y;
            }
            xm3 = xm2; xm2 = xm1; xm1 = xh;
        }

        #pragma unroll 4
        for (int tt = 0; tt < 16; tt++) {
            const int t = t0 + tt;
            ull ax = 0ull, az = 0ull;
            const float4* xp4 = (const float4*)xin_s[t];
            #pragma unroll
            for (int qq = 0; qq < 8; qq++) {
                float4 xv4 = xp4[qq];
                ull lo = pack2(xv4.x, xv4.y);
                ull hi = pack2(xv4.z, xv4.w);
                FMA2(ax, wa[2 * qq], lo, ax);
                FMA2(az, wz[2 * qq], lo, az);
                FMA2(ax, wa[2 * qq + 1], hi, ax);
                FMA2(az, wz[2 * qq + 1], hi, az);
            }
            float2 fx = unpack2(ax), fz = unpack2(az);
            const float xh = fx.x + fx.y;
            const float z = fz.x + fz.y;
            float xc = cb;
            xc = fmaf(cw.x, xm3, xc);
            xc = fmaf(cw.y, xm2, xc);
            xc = fmaf(cw.z, xm1, xc);
            xc = fmaf(cw.w, xh, xc);
            xm3 = xm2; xm2 = xm1; xm1 = xh;
            const float xt = __fdividef(xc, 1.f + __expf(-xc));
            xt_s[t][xpos] = xt;
            pkg[t * REC + d] = xt;
            pkg[t * REC + 64 + d] = __fdividef(z, 1.f + __expf(-z));
        }
    }
    __syncthreads();

    // ---- phase B: x_proj half-rows + dt for t in [16g, 16g+16) ----
    {
        const int i = tid & 63;
        const int l = tid & 31;
        const int ihalf = (tid >> 5) & 1;
        ull wB[16];
        #pragma unroll
        for (int qq = 0; qq < 8; qq++) {
            float4 b4 = xpw4[qq][i];
            wB[2 * qq] = pack2(b4.x, b4.y);
            wB[2 * qq + 1] = pack2(b4.z, b4.w);
        }
        const float2 wdv = unpack2(wdt_u[i]);
        const uint32_t xt_a = (uint32_t)__cvta_generic_to_shared(&xt_s[0][0]);
        const uint32_t hoff = (uint32_t)(i & 1) * 16u;
        const int d0 = 2 * l;
        const int dtf = (d0 < 32) ? ((d0 >> 2) * 8 + (d0 & 3))
                                  : (((d0 - 32) >> 2) * 8 + 4 + (d0 & 3));
        const int pos = 16 * ihalf + (l >> 1);

        #pragma unroll 4
        for (int tt = 0; tt < 16; tt++) {
            const int t = 16 * g + tt;
            const uint32_t rowa = xt_a + (uint32_t)t * 256u;
            ull acc = 0ull;
            #pragma unroll
            for (int qq = 0; qq < 8; qq++) {
                float4 xv4 = lds128(rowa + (uint32_t)qq * 32u + hoff);
                FMA2(acc, wB[2 * qq], pack2(xv4.x, xv4.y), acc);
                FMA2(acc, wB[2 * qq + 1], pack2(xv4.z, xv4.w), acc);
            }
            float2 a2 = unpack2(acc);
            float partial = a2.x + a2.y;
            partial += __shfl_xor_sync(0xffffffffu, partial, 1);
            if (!(l & 1)) pkg[t * REC + 128 + pos] = partial;

            float2 xv = unpack2(lds64(rowa + (uint32_t)dtf * 4u));
            float u = fmaf(wdv.y, xv.y, wdv.x * xv.x);
            #pragma unroll
            for (int off = 16; off; off >>= 1)
                u += __shfl_xor_sync(0xffffffffu, u, off);
            if (l == 0) pkg[t * REC + 160 + ihalf] = u;
        }
    }
}

// ---------------- K2: scan with cp.async tile staging ----------------
__global__ __launch_bounds__(256, 2) void scan_kernel(
    const float* __restrict__ dt_proj_w, const float* __restrict__ dt_proj_b,
    const float* __restrict__ A_log, const float* __restrict__ Dp,
    const float* __restrict__ out_proj_w, const float* __restrict__ lin1_w,
    const float* __restrict__ lin1_b, const float* __restrict__ lin2_w,
    const float* __restrict__ lin2_b, float* __restrict__ out)
{
    __shared__ float stg[2][4][TK][REC];   // 45KB staged records
    __shared__ float part_s[4][SEQ][2];
    __shared__ float wm_s[DM];
    __shared__ float v_s[DI];
    __shared__ float a_s[DI][18];
    __shared__ float c_s;
    __shared__ int   slow_s;

    const int tid = threadIdx.x;
    const int team = tid >> 6;
    const int d = tid & 63;
    const int w = (tid >> 5) & 1;
    const int l = tid & 31;
    const int bb0 = blockIdx.x * 4;

    if (tid == 0) slow_s = 0;
    if (tid < DM) {
        float acc = 0.f;
        #pragma unroll
        for (int k = 0; k < 16; k++) acc = fmaf(lin2_w[k], lin1_w[k * 32 + tid], acc);
        wm_s[tid] = acc;
    }
    if (tid == 0) {
        float c = lin2_b[0];
        #pragma unroll
        for (int k = 0; k < 16; k++) c = fmaf(lin2_w[k], lin1_b[k], c);
        c_s = c;
    }
    __syncthreads();
    if (tid < DI) {
        float acc = 0.f;
        #pragma unroll
        for (int m = 0; m < 32; m++) acc = fmaf(wm_s[m], out_proj_w[m * 64 + tid], acc);
        v_s[tid] = acc;
        int bad = 0;
        #pragma unroll
        for (int n = 0; n < 16; n++) {
            float a = -__expf(A_log[tid * 16 + n]);
            a_s[tid][n] = a;
            if (fabsf(a + (float)(n + 1)) > 1e-4f * (float)(n + 1)) bad = 1;
        }
        if (bad) atomicOr(&slow_s, 1);
    }

    const uint32_t stg_a = (uint32_t)__cvta_generic_to_shared(&stg[0][0][0][0]);
    const float4* gbase = (const float4*)g_pk;

    // fill buffer 0 (tile 0)
    #pragma unroll
    for (int q = tid; q < 4 * TK * RECF4; q += 256) {
        int s = q / (TK * RECF4), r = q % (TK * RECF4);
        cpasync16(stg_a + (uint32_t)q * 16u,
                  gbase + ((size_t)(bb0 + s) * SEQ + 0) * RECF4 + r);
    }
    CP_COMMIT();
    CP_WAIT0();
    __syncthreads();

    const float2 dtw = *(const float2*)(dt_proj_w + d * 2);
    const float dtb = dt_proj_b[d];
    const float dpv = Dp[d];
    const float vv = v_s[d];
    const int slow = slow_s;

    ull h2[8];
    #pragma unroll
    for (int q = 0; q < 8; q++) h2[q] = 0ull;

    for (int tile = 0; tile < SEQ / TK; tile++) {
        const int buf = tile & 1;
        // prefetch next tile into other buffer
        if (tile + 1 < SEQ / TK) {
            const uint32_t dsta = stg_a + (uint32_t)(buf ^ 1) * (4 * TK * REC * 4);
            #pragma unroll
            for (int q = tid; q < 4 * TK * RECF4; q += 256) {
                int s = q / (TK * RECF4), r = q % (TK * RECF4);
                cpasync16(dsta + (uint32_t)q * 16u,
                          gbase + ((size_t)(bb0 + s) * SEQ + (tile + 1) * TK) * RECF4 + r);
            }
            CP_COMMIT();
        }

        // scan current tile
        const uint32_t tbase = stg_a + (uint32_t)buf * (4 * TK * REC * 4)
                             + (uint32_t)team * (TK * REC * 4);
        #pragma unroll
        for (int tt = 0; tt < TK; tt++) {
            const uint32_t rowa = tbase + (uint32_t)tt * (REC * 4);
            float4 b40 = lds128(rowa + 512), b41 = lds128(rowa + 528);
            float4 b42 = lds128(rowa + 544), b43 = lds128(rowa + 560);
            float4 c40 = lds128(rowa + 576), c41 = lds128(rowa + 592);
            float4 c42 = lds128(rowa + 608), c43 = lds128(rowa + 624);
            const float2 uu = unpack2(lds64(rowa + 640));
            float xt, sz;
            asm volatile("ld.shared.f32 %0, [%1];" : "=f"(xt) : "r"(rowa + (uint32_t)d * 4u));
            asm volatile("ld.shared.f32 %0, [%1];" : "=f"(sz) : "r"(rowa + 256u + (uint32_t)d * 4u));

            const float dpre = fmaf(dtw.x, uu.x, fmaf(dtw.y, uu.y, dtb));
            const float delta = dpre > 15.f ? dpre : __logf(1.f + __expf(dpre));
            const float du = delta * xt;
            const ull du2 = pack2(du, du);
            ull y2a = 0ull, y2b = 0ull;

            if (!slow) {
                const float r = __expf(-delta);
                const float rr = r * r;
                ull cur = pack2(r, rr);
                const ull rrd = pack2(rr, rr);
                #pragma unroll
                for (int qq = 0; qq < 4; qq++) {
                    float4 b4 = (qq == 0) ? b40 : (qq == 1) ? b41 : (qq == 2) ? b42 : b43;
                    float4 c4 = (qq == 0) ? c40 : (qq == 1) ? c41 : (qq == 2) ? c42 : c43;
                    ull bp = pack2(b4.x, b4.y), cp = pack2(c4.x, c4.y);
                    ull tmp;
                    MUL2(tmp, bp, du2);
                    FMA2(h2[2 * qq], cur, h2[2 * qq], tmp);
                    FMA2(y2a, h2[2 * qq], cp, y2a);
                    MUL2(cur, cur, rrd);
                    bp = pack2(b4.z, b4.w); cp = pack2(c4.z, c4.w);
                    MUL2(tmp, bp, du2);
                    FMA2(h2[2 * qq + 1], cur, h2[2 * qq + 1], tmp);
                    FMA2(y2b, h2[2 * qq + 1], cp, y2b);
                    if (qq < 3) MUL2(cur, cur, rrd);
                }
            } else {
                #pragma unroll
                for (int qq = 0; qq < 4; qq++) {
                    float4 b4 = (qq == 0) ? b40 : (qq == 1) ? b41 : (qq == 2) ? b42 : b43;
                    float4 c4 = (qq == 0) ? c40 : (qq == 1) ? c41 : (qq == 2) ? c42 : c43;
                    float4 ap = *(const float4*)&a_s[d][4 * qq];
                    ull dA = pack2(__expf(delta * ap.x), __expf(delta * ap.y));
                    ull bp = pack2(b4.x, b4.y), cp = pack2(c4.x, c4.y);
                    ull tmp;
                    MUL2(tmp, bp, du2);
                    FMA2(h2[2 * qq], dA, h2[2 * qq], tmp);
                    FMA2(y2a, h2[2 * qq], cp, y2a);
                    dA = pack2(__expf(delta * ap.z), __expf(delta * ap.w));
                    bp = pack2(b4.z, b4.w); cp = pack2(c4.z, c4.w);
                    MUL2(tmp, bp, du2);
                    FMA2(h2[2 * qq + 1], dA, h2[2 * qq + 1], tmp);
                    FMA2(y2b, h2[2 * qq + 1], cp, y2b);
                }
            }
            float2 ya = unpack2(y2a), yb = unpack2(y2b);
            float y = (ya.x + ya.y) + (yb.x + yb.y);
            y = fmaf(xt, dpv, y);
            y *= sz;

            float acc = y * vv;
            #pragma unroll
            for (int off = 16; off; off >>= 1)
                acc += __shfl_xor_sync(0xffffffffu, acc, off);
            if (l == 0) part_s[team][tile * TK + tt][w] = acc;
        }

        if (tile + 1 < SEQ / TK) CP_WAIT0();
        __syncthreads();
    }

    {
        const int tt = tid >> 2;
        const int jj = tid & 3;
        const float val = part_s[jj][tt][0] + part_s[jj][tt][1] + c_s;
        const int obb = bb0 + jj;
        out[(obb >> 10) * (SEQ * HW) + tt * HW + (obb & (HW - 1))] = val;
    }
}

extern "C" void kernel_launch(void* const* d_in, const int* in_sizes, int n_in,
                              void* d_out, int out_size) {
    const float* x         = (const float*)d_in[0];
    const float* in_proj_w = (const float*)d_in[1];
    const float* conv_w    = (const float*)d_in[2];
    const float* conv_b    = (const float*)d_in[3];
    const float* x_proj_w  = (const float*)d_in[4];
    const float* dt_proj_w = (const float*)d_in[5];
    const float* dt_proj_b = (const float*)d_in[6];
    const float* A_log     = (const float*)d_in[7];
    const float* Dp        = (const float*)d_in[8];
    const float* out_proj_w= (const float*)d_in[9];
    const float* lin1_w    = (const float*)d_in[10];
    const float* lin1_b    = (const float*)d_in[11];
    const float* lin2_w    = (const float*)d_in[12];
    const float* lin2_b    = (const float*)d_in[13];
    float* out = (float*)d_out;

    transpose_kernel<<<2048, 256>>>(x);
    prelude_kernel<<<2048, 256>>>(in_proj_w, conv_w, conv_b, x_proj_w);
    scan_kernel<<<512, 256>>>(dt_proj_w, dt_proj_b, A_log, Dp, out_proj_w,
                              lin1_w, lin1_b, lin2_w, lin2_b, out);
}